// round 9
// baseline (speedup 1.0000x reference)
#include <cuda_runtime.h>

// Fixed shapes.
#define Bv 2
#define Cv 3
#define Dv 128
#define Hv 192
#define Wv 192
#define HW (Hv * Wv)          // 36864
#define PS 196                // xz tile row stride: 196 == 4 (mod 32)

// ---------------------------------------------------------------------------
// Kernel A: y-solve (along H), field -> out. One CTA per (b,c,d, w-half).
// Tile: H x 96 (74KB) -> occupancy 3. 96 threads; thread t owns pencil w = t.
// ---------------------------------------------------------------------------
__global__ __launch_bounds__(96, 3)
void y_solve_kernel(const float* __restrict__ in, float* __restrict__ out,
                    const float* __restrict__ ay, const float* __restrict__ by,
                    const float* __restrict__ cy)
{
    extern __shared__ float sm[];
    float* tile  = sm;                 // Hv * 96
    float* s_cys = tile + Hv * 96;     // 192: cy[i-1], [0] unused
    float* s_iay = s_cys + Hv;         // 192: 1/ay
    float* s_fy  = s_iay + Hv;         // 192: by/ay, [191] unused

    const int t = threadIdx.x;

    for (int i = t; i < Hv; i += 96) {
        float a = ay[i];
        s_iay[i] = 1.0f / a;
        s_cys[i] = (i >= 1)     ? cy[i - 1] : 0.0f;
        s_fy[i]  = (i < Hv - 1) ? by[i] / a : 0.0f;
    }

    const int slice = blockIdx.x >> 1;          // (b,c,d) slice id
    const int half  = blockIdx.x & 1;           // w-half 0/1
    const size_t f4base = (size_t)slice * (HW / 4) + (size_t)half * 24;

    // Load: 48 float4 per thread, fully independent (deep MLP), coalesced.
    {
        const float4* g4 = (const float4*)in;
        #pragma unroll
        for (int k = 0; k < 48; k++) {
            const int lin = k * 96 + t;         // 0 .. 4607
            const int h   = lin / 24;
            const int j   = lin % 24;
            float4 v = g4[f4base + (size_t)h * 48 + j];
            *(float4*)(tile + h * 96 + 4 * j) = v;
        }
    }
    __syncthreads();

    // y-sweep: thread t owns pencil w = half*96 + t.
    {
        float carry = tile[t];
        #pragma unroll 8
        for (int i = 1; i < Hv; i++) {
            carry = fmaf(-s_cys[i], carry, tile[i * 96 + t]);
            tile[i * 96 + t] = carry;
        }
        float* o = out + (size_t)slice * HW + half * 96 + t;
        carry = carry * s_iay[Hv - 1];
        o[(size_t)(Hv - 1) * Wv] = carry;
        #pragma unroll 8
        for (int i = Hv - 2; i >= 0; i--) {
            carry = fmaf(-s_fy[i], carry, tile[i * 96 + t] * s_iay[i]);
            o[(size_t)i * Wv] = carry;
        }
    }
}

// ---------------------------------------------------------------------------
// Kernel B: fused x-solve (W) + z-solve (D), in-place on out.
// One CTA per (b,c,h) slab; tile D x W (stride 196, 98KB) -> occupancy 2.
//  - x-sweep: threads t<128 own d-row t (float4 vector sweeps)
//  - z-sweep: all 192 threads own w-column t; bwd fused with coalesced STG
// ---------------------------------------------------------------------------
__global__ __launch_bounds__(192, 2)
void xz_solve_kernel(float* __restrict__ io,
                     const float* __restrict__ ax, const float* __restrict__ bx,
                     const float* __restrict__ cx,
                     const float* __restrict__ az, const float* __restrict__ bz,
                     const float* __restrict__ cz)
{
    extern __shared__ float sm[];
    float* tile  = sm;                 // Dv * PS
    float* s_cxs = tile + Dv * PS;     // 192: cx[i-1], [0] unused
    float* s_iax = s_cxs + Wv;         // 192: 1/ax
    float* s_fx  = s_iax + Wv;         // 192: bx/ax, [191] unused
    float* s_cz  = s_fx + Wv;          // 128: cz[d-1], [0] unused
    float* s_iaz = s_cz + Dv;          // 128: 1/az
    float* s_fz  = s_iaz + Dv;         // 128: bz/az, [127] unused

    const int t = threadIdx.x;

    if (t < Wv) {
        float a = ax[t];
        s_iax[t] = 1.0f / a;
        s_cxs[t] = (t >= 1)     ? cx[t - 1] : 0.0f;
        s_fx[t]  = (t < Wv - 1) ? bx[t] / a : 0.0f;
    }
    if (t < Dv) {
        float a = az[t];
        s_iaz[t] = 1.0f / a;
        s_cz[t]  = (t >= 1)     ? cz[t - 1] : 0.0f;
        s_fz[t]  = (t < Dv - 1) ? bz[t] / a : 0.0f;
    }

    const int h  = blockIdx.x % Hv;
    const int bc = blockIdx.x / Hv;
    const size_t base   = (size_t)bc * (Dv * HW) + (size_t)h * Wv;  // float offset
    const size_t f4base = base >> 2;

    // Load: 32 float4 per thread, independent, coalesced (192 floats/row).
    {
        const float4* g4 = (const float4*)io;
        #pragma unroll
        for (int k = 0; k < 32; k++) {
            const int lin = k * 192 + t;        // 0 .. 6143
            const int d   = lin / 48;
            const int j   = lin % 48;
            float4 v = g4[f4base + (size_t)d * (HW / 4) + j];
            *(float4*)(tile + d * PS + 4 * j) = v;
        }
    }
    __syncthreads();

    // ---- x-solve: thread t<128 owns d-row t ---------------------------------
    if (t < Dv) {
        float* row = tile + t * PS;
        float carry = row[0];
        #pragma unroll
        for (int i = 1; i < 4; i++) {
            carry = fmaf(-s_cxs[i], carry, row[i]);
            row[i] = carry;
        }
        #pragma unroll 4
        for (int g = 4; g < Wv; g += 4) {
            float4 v  = *(const float4*)(row + g);
            float4 cc = *(const float4*)(s_cxs + g);
            v.x = fmaf(-cc.x, carry, v.x);
            v.y = fmaf(-cc.y, v.x, v.y);
            v.z = fmaf(-cc.z, v.y, v.z);
            v.w = fmaf(-cc.w, v.z, v.w);
            carry = v.w;
            *(float4*)(row + g) = v;
        }
        carry = carry * s_iax[Wv - 1];
        row[Wv - 1] = carry;
        #pragma unroll
        for (int i = Wv - 2; i >= Wv - 4; i--) {
            carry = fmaf(-s_fx[i], carry, row[i] * s_iax[i]);
            row[i] = carry;
        }
        #pragma unroll 4
        for (int g = Wv - 8; g >= 0; g -= 4) {
            float4 v  = *(const float4*)(row + g);
            float4 ff = *(const float4*)(s_fx + g);
            float4 ia = *(const float4*)(s_iax + g);
            v.w = fmaf(-ff.w, carry, v.w * ia.w);
            v.z = fmaf(-ff.z, v.w, v.z * ia.z);
            v.y = fmaf(-ff.y, v.z, v.y * ia.y);
            v.x = fmaf(-ff.x, v.y, v.x * ia.x);
            carry = v.x;
            *(float4*)(row + g) = v;
        }
    }
    __syncthreads();

    // ---- z-solve: thread t owns w-column t; bwd streams to global -----------
    {
        float carry = tile[t];
        #pragma unroll 8
        for (int d = 1; d < Dv; d++) {
            carry = fmaf(-s_cz[d], carry, tile[d * PS + t]);
            tile[d * PS + t] = carry;
        }
        float* o = io + base + t;
        carry = carry * s_iaz[Dv - 1];
        o[(size_t)(Dv - 1) * HW] = carry;
        #pragma unroll 8
        for (int d = Dv - 2; d >= 0; d--) {
            carry = fmaf(-s_fz[d], carry, tile[d * PS + t] * s_iaz[d]);
            o[(size_t)d * HW] = carry;
        }
    }
}

// ---------------------------------------------------------------------------
extern "C" void kernel_launch(void* const* d_in, const int* in_sizes, int n_in,
                              void* d_out, int out_size)
{
    const float* field = (const float*)d_in[0];
    const float* ax = (const float*)d_in[1];
    const float* bx = (const float*)d_in[2];
    const float* cx = (const float*)d_in[3];
    const float* ay = (const float*)d_in[4];
    const float* by = (const float*)d_in[5];
    const float* cy = (const float*)d_in[6];
    const float* az = (const float*)d_in[7];
    const float* bz = (const float*)d_in[8];
    const float* cz = (const float*)d_in[9];
    float* out = (float*)d_out;

    const int smem_y  = (Hv * 96 + 3 * Hv) * (int)sizeof(float);           // ~74.3KB
    const int smem_xz = (Dv * PS + 3 * Wv + 3 * Dv) * (int)sizeof(float);  // ~104KB

    cudaFuncSetAttribute(y_solve_kernel,
                         cudaFuncAttributeMaxDynamicSharedMemorySize, smem_y);
    cudaFuncSetAttribute(xz_solve_kernel,
                         cudaFuncAttributeMaxDynamicSharedMemorySize, smem_xz);

    // Axis solves commute (tensor-product operators): order y, then x+z.
    y_solve_kernel<<<Bv * Cv * Dv * 2, 96, smem_y>>>(field, out, ay, by, cy);
    xz_solve_kernel<<<Bv * Cv * Hv, 192, smem_xz>>>(out, ax, bx, cx, az, bz, cz);
}

// round 10
// speedup vs baseline: 1.3186x; 1.3186x over previous
#include <cuda_runtime.h>
#include <cuda_fp16.h>

// Fixed shapes.
#define Bv 2
#define Cv 3
#define Dv 128
#define Hv 192
#define Wv 192
#define HW (Hv * Wv)
#define SP 200             // fp16 tile row stride in halves: 100 words == 4 (mod 32)
                           // -> conflict-free 16B row sweeps AND column access

// ---------------------------------------------------------------------------
// Kernel 1: fused x-solve (W) + y-solve (H), one CTA per (b,c,d) slice.
// Tile stored as fp16 (76.8KB) -> occupancy 2; all math in fp32.
// ---------------------------------------------------------------------------
__global__ __launch_bounds__(192, 2)
void xy_solve_kernel(const float* __restrict__ in, float* __restrict__ out,
                     const float* __restrict__ ax, const float* __restrict__ bx,
                     const float* __restrict__ cx,
                     const float* __restrict__ ay, const float* __restrict__ by,
                     const float* __restrict__ cy)
{
    extern __shared__ __align__(16) unsigned char smraw[];
    __half* tile = (__half*)smraw;                       // Hv * SP halves
    float*  fco  = (float*)(smraw + Hv * SP * 2);        // 6 * 192 floats
    float* s_cxs = fco;            // [i] = cx[i-1], [0] unused
    float* s_iax = fco + 192;      // 1/ax
    float* s_fx  = fco + 384;      // bx/ax, [191] unused
    float* s_cys = fco + 576;      // cy shifted
    float* s_iay = fco + 768;      // 1/ay
    float* s_fy  = fco + 960;      // by/ay, [191] unused

    const int t = threadIdx.x;

    if (t < Wv) {
        float a = ax[t];
        s_iax[t] = 1.0f / a;
        s_cxs[t] = (t >= 1)     ? cx[t - 1] : 0.0f;
        s_fx[t]  = (t < Wv - 1) ? bx[t] / a : 0.0f;
    }
    if (t < Hv) {
        float a = ay[t];
        s_iay[t] = 1.0f / a;
        s_cys[t] = (t >= 1)     ? cy[t - 1] : 0.0f;
        s_fy[t]  = (t < Hv - 1) ? by[t] / a : 0.0f;
    }

    // ---- load: fp32 float4 from gmem -> fp16x4 into tile (deep MLP) --------
    {
        const float4* g4 = (const float4*)(in + (size_t)blockIdx.x * HW);
        const int c4 = t % 48;            // float4 column 0..47
        const int r0 = t / 48;            // row-within-group 0..3
        #pragma unroll
        for (int it = 0; it < 48; it++) {
            const int k = it * 4 + r0;    // row
            float4 v = g4[k * 48 + c4];
            __half2 h01 = __floats2half2_rn(v.x, v.y);
            __half2 h23 = __floats2half2_rn(v.z, v.w);
            *(__half2*)(tile + k * SP + c4 * 4)     = h01;   // 8B-aligned pair
            *(__half2*)(tile + k * SP + c4 * 4 + 2) = h23;
        }
    }
    __syncthreads();

    // ---- x-solve: thread t owns row h = t -----------------------------------
    {
        __half* row = tile + t * SP;
        // forward: scalar head 0..7, then 8-wide groups 8..191
        float carry = __half2float(row[0]);
        #pragma unroll
        for (int i = 1; i < 8; i++) {
            carry = fmaf(-s_cxs[i], carry, __half2float(row[i]));
            row[i] = __float2half_rn(carry);
        }
        #pragma unroll 2
        for (int g = 8; g < Wv; g += 8) {
            uint4 raw = *(const uint4*)(row + g);            // 8 halves, 16B
            __half2* hp = (__half2*)&raw;
            float2 p0 = __half22float2(hp[0]);
            float2 p1 = __half22float2(hp[1]);
            float2 p2 = __half22float2(hp[2]);
            float2 p3 = __half22float2(hp[3]);
            p0.x = fmaf(-s_cxs[g + 0], carry, p0.x);
            p0.y = fmaf(-s_cxs[g + 1], p0.x,  p0.y);
            p1.x = fmaf(-s_cxs[g + 2], p0.y,  p1.x);
            p1.y = fmaf(-s_cxs[g + 3], p1.x,  p1.y);
            p2.x = fmaf(-s_cxs[g + 4], p1.y,  p2.x);
            p2.y = fmaf(-s_cxs[g + 5], p2.x,  p2.y);
            p3.x = fmaf(-s_cxs[g + 6], p2.y,  p3.x);
            p3.y = fmaf(-s_cxs[g + 7], p3.x,  p3.y);
            carry = p3.y;
            hp[0] = __floats2half2_rn(p0.x, p0.y);
            hp[1] = __floats2half2_rn(p1.x, p1.y);
            hp[2] = __floats2half2_rn(p2.x, p2.y);
            hp[3] = __floats2half2_rn(p3.x, p3.y);
            *(uint4*)(row + g) = raw;
        }
        // backward: scalar head 191..184, then 8-wide groups 176..0
        carry = carry * s_iax[Wv - 1];
        row[Wv - 1] = __float2half_rn(carry);
        #pragma unroll
        for (int i = Wv - 2; i >= Wv - 8; i--) {
            carry = fmaf(-s_fx[i], carry, __half2float(row[i]) * s_iax[i]);
            row[i] = __float2half_rn(carry);
        }
        #pragma unroll 2
        for (int g = Wv - 16; g >= 0; g -= 8) {
            uint4 raw = *(const uint4*)(row + g);
            __half2* hp = (__half2*)&raw;
            float2 p0 = __half22float2(hp[0]);
            float2 p1 = __half22float2(hp[1]);
            float2 p2 = __half22float2(hp[2]);
            float2 p3 = __half22float2(hp[3]);
            p3.y = fmaf(-s_fx[g + 7], carry, p3.y * s_iax[g + 7]);
            p3.x = fmaf(-s_fx[g + 6], p3.y,  p3.x * s_iax[g + 6]);
            p2.y = fmaf(-s_fx[g + 5], p3.x,  p2.y * s_iax[g + 5]);
            p2.x = fmaf(-s_fx[g + 4], p2.y,  p2.x * s_iax[g + 4]);
            p1.y = fmaf(-s_fx[g + 3], p2.x,  p1.y * s_iax[g + 3]);
            p1.x = fmaf(-s_fx[g + 2], p1.y,  p1.x * s_iax[g + 2]);
            p0.y = fmaf(-s_fx[g + 1], p1.x,  p0.y * s_iax[g + 1]);
            p0.x = fmaf(-s_fx[g + 0], p0.y,  p0.x * s_iax[g + 0]);
            carry = p0.x;
            hp[0] = __floats2half2_rn(p0.x, p0.y);
            hp[1] = __floats2half2_rn(p1.x, p1.y);
            hp[2] = __floats2half2_rn(p2.x, p2.y);
            hp[3] = __floats2half2_rn(p3.x, p3.y);
            *(uint4*)(row + g) = raw;
        }
    }
    __syncthreads();

    // ---- y-solve: thread t owns column w = t; bwd streams fp32 to gmem ------
    {
        float carry = __half2float(tile[t]);
        #pragma unroll 8
        for (int i = 1; i < Hv; i++) {
            carry = fmaf(-s_cys[i], carry, __half2float(tile[i * SP + t]));
            tile[i * SP + t] = __float2half_rn(carry);
        }
        float* o = out + (size_t)blockIdx.x * HW;
        carry = carry * s_iay[Hv - 1];
        o[(Hv - 1) * Wv + t] = carry;
        #pragma unroll 8
        for (int i = Hv - 2; i >= 0; i--) {
            carry = fmaf(-s_fy[i], carry,
                         __half2float(tile[i * SP + t]) * s_iay[i]);
            o[i * Wv + t] = carry;
        }
    }
}

// ---------------------------------------------------------------------------
// Kernel 2: z-solve (D), in-place. Register-resident column per thread.
// (Unchanged since R5: 36.4us, DRAM 58% — protected.)
// ---------------------------------------------------------------------------
__global__ __launch_bounds__(192, 2)
void z_solve_kernel(float* __restrict__ io,
                    const float* __restrict__ az, const float* __restrict__ bz,
                    const float* __restrict__ cz)
{
    __shared__ float s_c[Dv - 1];
    __shared__ float s_ia[Dv];
    __shared__ float s_f[Dv - 1];

    const int t = threadIdx.x;
    if (t < Dv)     { s_ia[t] = 1.0f / az[t]; }
    if (t < Dv - 1) { s_c[t] = cz[t]; s_f[t] = bz[t] / az[t]; }
    __syncthreads();

    const int n  = blockIdx.x;            // over B*C*H
    const int h  = n % Hv;
    const int bc = n / Hv;
    float* g = io + (size_t)bc * (Dv * HW) + (size_t)h * Wv + t;

    float y[Dv];
    #pragma unroll
    for (int d = 0; d < Dv; d++)
        y[d] = g[(size_t)d * HW];

    #pragma unroll
    for (int d = 1; d < Dv; d++)
        y[d] = fmaf(-s_c[d - 1], y[d - 1], y[d]);

    float carry = y[Dv - 1] * s_ia[Dv - 1];
    g[(size_t)(Dv - 1) * HW] = carry;
    #pragma unroll
    for (int d = Dv - 2; d >= 0; d--) {
        carry = fmaf(-s_f[d], carry, y[d] * s_ia[d]);
        g[(size_t)d * HW] = carry;
    }
}

// ---------------------------------------------------------------------------
extern "C" void kernel_launch(void* const* d_in, const int* in_sizes, int n_in,
                              void* d_out, int out_size)
{
    const float* field = (const float*)d_in[0];
    const float* ax = (const float*)d_in[1];
    const float* bx = (const float*)d_in[2];
    const float* cx = (const float*)d_in[3];
    const float* ay = (const float*)d_in[4];
    const float* by = (const float*)d_in[5];
    const float* cy = (const float*)d_in[6];
    const float* az = (const float*)d_in[7];
    const float* bz = (const float*)d_in[8];
    const float* cz = (const float*)d_in[9];
    float* out = (float*)d_out;

    const int smem_xy = Hv * SP * 2 + 6 * 192 * (int)sizeof(float);  // ~81.4KB

    cudaFuncSetAttribute(xy_solve_kernel,
                         cudaFuncAttributeMaxDynamicSharedMemorySize, smem_xy);

    xy_solve_kernel<<<Bv * Cv * Dv, 192, smem_xy>>>(field, out,
                                                    ax, bx, cx, ay, by, cy);
    z_solve_kernel<<<Bv * Cv * Hv, 192>>>(out, az, bz, cz);
}